// round 15
// baseline (speedup 1.0000x reference)
#include <cuda_runtime.h>
#include <cstdint>

#define NB 64
#define NT 4096
#define NS 64
#define NTHREADS 128

__device__ __forceinline__ void fma2(unsigned long long &d, unsigned long long a, unsigned long long b) {
    asm("fma.rn.f32x2 %0, %1, %2, %0;" : "+l"(d) : "l"(a), "l"(b));
}
__device__ __forceinline__ unsigned long long add2(unsigned long long a, unsigned long long b) {
    unsigned long long d;
    asm("add.rn.f32x2 %0, %1, %2;" : "=l"(d) : "l"(a), "l"(b));
    return d;
}
__device__ __forceinline__ unsigned long long pk2(float lo, float hi) {
    unsigned long long d;
    asm("mov.b64 %0, {%1, %2};" : "=l"(d) : "f"(lo), "f"(hi));
    return d;
}

__global__ __launch_bounds__(NTHREADS, 1) void hmm_forward_kernel(
    const float* __restrict__ trans,   // (S,S)
    const float* __restrict__ emis,    // (B,T,S)
    float* __restrict__ alpha_out,     // (B,T,S)
    float* __restrict__ logz_out)      // (B,)
{
    const int b = blockIdx.x;
    const int tid = threadIdx.x;
    const int j = tid & (NS - 1);     // state 0..63
    const int q = tid >> 6;           // 0 = chain warps (SMSP 0,1), 1 = output warps (SMSP 2,3)

    __shared__ __align__(16) float su[2][NS];  // u_t = exp(alpha_t - N_t), parity buffered
    __shared__ float D[4];                     // d ring: D[s&3] = r_{s-1} - r_{s-2}
    __shared__ float sred[NS];                 // final logsumexp scratch

    const float* eb = emis + (size_t)b * NT * NS;
    float* ob = alpha_out + (size_t)b * NT * NS;

    if (tid < 4) D[tid] = 0.0f;       // d_1..d_4-ish seeds (r_{-k} = r_0)

    // ---- chain-warp registers ----
    unsigned long long eA[NS / 2];    // eA[k] = (e^A[2k][j], e^A[2k+1][j])
    float f = 0.0f;                   // f_t for the upcoming phase
    float ebuf[4] = {0, 0, 0, 0};     // slot s&3 holds e_s (consumed for f_{s})

    // ---- output-warp registers ----
    float N_cur = 0.0f;               // N_{t-1} tracked by q1
    float r_prev = 0.0f;              // r_{t-2}, held by tid==64 (j==0 of q1)

    const float N0 = eb[0];           // alpha_0[0] (broadcast LDG)

    if (q == 0) {
#pragma unroll
        for (int k = 0; k < NS / 2; k++) {
            float e0 = __expf(trans[(2 * k) * NS + j]);
            float e1 = __expf(trans[(2 * k + 1) * NS + j]);
            eA[k] = pk2(e0, e1);
        }
        float a0j = eb[j];                      // alpha_0[j] = e_0[j]
        su[0][j] = __expf(a0j - N0);            // u_0 (exact invariant, N_0 = alpha_0[0])
        f = __expf(eb[(size_t)1 * NS + j]);     // f_1 = exp(e_1 - 0)
        // prefetch e_2..e_5 into slots s&3
#pragma unroll
        for (int p = 2; p <= 5; p++) ebuf[p & 3] = eb[(size_t)p * NS + j];
    } else {
        ob[j] = eb[j];                          // alpha_0 output
        N_cur = N0;                             // N_0
        r_prev = N0;                            // r_0 (only meaningful on tid==64)
    }
    __syncthreads();

    // ---- Main recurrence: phase t computes u_t (q0) and alpha_{t-1} (q1) ----
#pragma unroll 2
    for (int t = 1; t < NT; t++) {
        const int buf = t & 1;
        if (q == 0) {
            // s_j(t) = sum_i u_i(t-1) * e^A[i][j]
            const ulonglong2* sp = reinterpret_cast<const ulonglong2*>(&su[buf ^ 1][0]);
            unsigned long long acc0 = 0ull, acc1 = 0ull, acc2 = 0ull, acc3 = 0ull;
#pragma unroll
            for (int k = 0; k < 8; k++) {
                ulonglong2 qa = sp[2 * k];
                ulonglong2 qb = sp[2 * k + 1];
                fma2(acc0, qa.x, eA[4 * k + 0]);
                fma2(acc1, qa.y, eA[4 * k + 1]);
                fma2(acc2, qb.x, eA[4 * k + 2]);
                fma2(acc3, qb.y, eA[4 * k + 3]);
            }
            unsigned long long s2 = add2(add2(acc0, acc1), add2(acc2, acc3));
            float lo, hi;
            asm("mov.b64 {%0, %1}, %2;" : "=f"(lo), "=f"(hi) : "l"(s2));
            float s = lo + hi;
            su[buf][j] = s * f;                       // u_t = s_t * f_t
            // prepare f_{t+1} = exp(e_{t+1} - d_{t+1}), d_{t+1} = D[(t-1)&3] (1 BAR old)
            if (t < NT - 1) {
                float d = D[(t - 1) & 3];
                float e_next = ebuf[(t + 1) & 3];
                ebuf[(t + 1) & 3] = (t + 5 <= NT - 1) ? eb[(size_t)(t + 5) * NS + j] : 0.0f;
                f = __expf(e_next - d);
            }
        } else if (t > 1) {
            // alpha_{t-1} = log u_{t-1} + N_{t-1};  N_{t-1} = N_{t-2} + D[(t-3)&3]
            N_cur += D[(t - 3) & 3];
            float u = su[buf ^ 1][j];                 // u_{t-1} (stable this phase)
            float aout = __logf(u) + N_cur;
            ob[(size_t)(t - 1) * NS + j] = aout;
            if (j == 0) {                             // publish D[t&3] = r_{t-1} - r_{t-2}
                D[t & 3] = aout - r_prev;
                r_prev = aout;
            }
        }
        __syncthreads();
    }

    // ---- Epilogue: alpha_{NT-1} and log_Z (q1 path) ----
    if (q == 1) {
        N_cur += D[(NT - 3) & 3];                     // N_{NT-1}
        float u = su[(NT - 1) & 1][j];
        float aout = __logf(u) + N_cur;
        ob[(size_t)(NT - 1) * NS + j] = aout;
        sred[j] = aout;
    }
    __syncthreads();
    if (tid == 0) {
        float mx = sred[0];
#pragma unroll
        for (int i = 1; i < NS; i++) mx = fmaxf(mx, sred[i]);
        float tot = 0.0f;
#pragma unroll
        for (int i = 0; i < NS; i++) tot += __expf(sred[i] - mx);
        logz_out[b] = mx + __logf(tot);
    }
}

extern "C" void kernel_launch(void* const* d_in, const int* in_sizes, int n_in,
                              void* d_out, int out_size) {
    const float* trans = (const float*)d_in[0];  // (S,S) fp32
    const float* emis  = (const float*)d_in[1];  // (B,T,S) fp32
    // d_in[2] = seq_lens (unused by reference)
    float* alpha = (float*)d_out;                       // (B,T,S)
    float* logz  = alpha + (size_t)NB * NT * NS;        // (B,)
    hmm_forward_kernel<<<NB, NTHREADS>>>(trans, emis, alpha, logz);
}

// round 16
// speedup vs baseline: 6.0248x; 6.0248x over previous
#include <cuda_runtime.h>
#include <cstdint>

#define NB 64
#define NT 4096
#define NS 64
#define CHUNK 256
#define NC (NT / CHUNK)   // 16 chunks; chunk c>0 warms up from t=(c-1)*CHUNK

__device__ float g_bnd[NB * NC * NS];   // g_bnd[b][c][:] = chunk (c-1)'s alpha' at t=c*CHUNK
__device__ float g_kappa[NB * NC];      // additive constant per chunk

__device__ __forceinline__ void fma2(unsigned long long &d, unsigned long long a, unsigned long long b) {
    asm("fma.rn.f32x2 %0, %1, %2, %0;" : "+l"(d) : "l"(a), "l"(b));
}
__device__ __forceinline__ unsigned long long add2(unsigned long long a, unsigned long long b) {
    unsigned long long d;
    asm("add.rn.f32x2 %0, %1, %2;" : "=l"(d) : "l"(a), "l"(b));
    return d;
}
__device__ __forceinline__ unsigned long long pk2(float lo, float hi) {
    unsigned long long d;
    asm("mov.b64 %0, {%1, %2};" : "=l"(d) : "f"(lo), "f"(hi));
    return d;
}

// ---------------- Pass 1: chunked forward (R10 exact-ring body, generalized t0) --------------
__global__ __launch_bounds__(NS) void hmm_chunk_kernel(
    const float* __restrict__ trans,
    const float* __restrict__ emis,
    float* __restrict__ alpha_out)
{
    const int c = blockIdx.x;          // chunk
    const int b = blockIdx.y;          // batch
    const int j = threadIdx.x;

    const int t0 = (c == 0) ? 0 : (c - 1) * CHUNK;     // warm-up start (c=0,1 are exact)
    const int emit0 = c * CHUNK;
    const int emitEnd = (c + 1) * CHUNK;               // bnd row (only reached if c < NC-1)
    const int tlast = (c < NC - 1) ? emitEnd : (NT - 1);

    __shared__ __align__(16) float su[2][NS];
    __shared__ float ring[4];

    unsigned long long eA[NS / 2];
#pragma unroll
    for (int k = 0; k < NS / 2; k++) {
        float e0 = __expf(trans[(2 * k) * NS + j]);
        float e1 = __expf(trans[(2 * k + 1) * NS + j]);
        eA[k] = pk2(e0, e1);
    }

    const float* eb = emis + (size_t)b * NT * NS;
    float* ob = alpha_out + (size_t)b * NT * NS;
    float* bnd = g_bnd + ((size_t)b * NC + (c + 1)) * NS;   // written only when c < NC-1

    // --- init at t0: alpha'_{t0} = e_{t0} (exact for c==0; warm-up init otherwise) ---
    float a0 = eb[(size_t)t0 * NS + j];
    float n0 = eb[(size_t)t0 * NS];          // component 0 broadcast
    if (c == 0) ob[j] = a0;                  // emit row t=0
    if (j == 0) {                            // ring seeds: r_{t0}=r_{t0-1}=r_{t0-2}=a0[0]
        ring[t0 & 3] = n0;
        ring[(t0 + 2) & 3] = n0;
        ring[(t0 + 3) & 3] = n0;
    }

    // slot (s-1)&3 holds e_s; init e_{t0+1}..e_{t0+4}
    float ebuf[4];
#pragma unroll
    for (int p = 0; p < 4; p++) ebuf[(t0 + p) & 3] = eb[(size_t)(t0 + 1 + p) * NS + j];

    __syncthreads();
    su[t0 & 1][j] = __expf(a0 - n0);                     // u(t0)
    float f = __expf(eb[(size_t)(t0 + 1) * NS + j]);     // f_{t0+1} = exp(e_{t0+1} - 0)
    __syncthreads();

    // exact stale-normalizer recurrence: u_t = exp(alpha_t - r_{t-2}); alpha_t = log s + r_{t-3} + e_t
#pragma unroll 2
    for (int t = t0 + 1; t <= tlast; t++) {
        const int buf = t & 1;
        const ulonglong2* sp = reinterpret_cast<const ulonglong2*>(&su[buf ^ 1][0]);
        unsigned long long acc0 = 0ull, acc1 = 0ull, acc2 = 0ull, acc3 = 0ull;
#pragma unroll
        for (int k = 0; k < 8; k++) {
            ulonglong2 qa = sp[2 * k];
            ulonglong2 qb = sp[2 * k + 1];
            fma2(acc0, qa.x, eA[4 * k + 0]);
            fma2(acc1, qa.y, eA[4 * k + 1]);
            fma2(acc2, qb.x, eA[4 * k + 2]);
            fma2(acc3, qb.y, eA[4 * k + 3]);
        }
        unsigned long long s2 = add2(add2(acc0, acc1), add2(acc2, acc3));
        float lo, hi;
        asm("mov.b64 {%0, %1}, %2;" : "=f"(lo), "=f"(hi) : "l"(s2));
        float s = lo + hi;

        su[buf][j] = s * f;            // u_t
        __syncthreads();

        float Nprev = ring[(t + 1) & 3];                 // r_{t-3}
        float e_cur = ebuf[(t - 1) & 3];                 // e_t
        float aout = __logf(s) + Nprev + e_cur;          // alpha'_t[j]
        if (t >= emit0) {
            if (t < emitEnd) ob[(size_t)t * NS + j] = aout;
            else             bnd[j] = aout;              // boundary row for chunk c+1
        }
        if (j == 0) ring[t & 3] = aout;

        ebuf[(t - 1) & 3] = (t + 4 < NT) ? eb[(size_t)(t + 4) * NS + j] : 0.0f;
        float dM = ring[(t - 1) & 3] - ring[(t - 2) & 3];
        f = __expf(ebuf[t & 3] - dM);
    }
}

// ---------------- Pass 2: serial offset scan over chunk boundaries ----------------
__global__ __launch_bounds__(32) void hmm_offset_kernel(const float* __restrict__ alpha)
{
    const int b = blockIdx.x;
    const int lane = threadIdx.x;
    float kap = 0.0f;
    if (lane == 0) g_kappa[b * NC] = 0.0f;               // chunk 0 exact
    for (int c = 1; c < NC; c++) {
        // delta_c = mean_j( bnd[b][c][j] - alpha'[b][c*CHUNK][j] )
        float d = 0.0f;
#pragma unroll
        for (int r = 0; r < 2; r++) {
            int jj = lane + 32 * r;
            d += g_bnd[((size_t)b * NC + c) * NS + jj]
               - alpha[((size_t)b * NT + c * CHUNK) * NS + jj];
        }
#pragma unroll
        for (int o = 16; o >= 1; o >>= 1) d += __shfl_xor_sync(0xFFFFFFFFu, d, o);
        kap += d * (1.0f / NS);
        if (lane == 0) g_kappa[b * NC + c] = kap;
    }
}

// ---------------- Pass 3: apply constants + log_Z ----------------
__global__ __launch_bounds__(256) void hmm_apply_kernel(
    float* __restrict__ alpha, float* __restrict__ logz)
{
    const int c = blockIdx.x;
    const int b = blockIdx.y;
    const int tid = threadIdx.x;
    const float kap = g_kappa[b * NC + c];

    float4* base = reinterpret_cast<float4*>(alpha + ((size_t)b * NT + c * CHUNK) * NS);
    __shared__ float last[NS];
    const int NV = CHUNK * NS / 4;       // 4096 float4 per chunk block
#pragma unroll
    for (int k = 0; k < NV / 256; k++) {
        int idx = k * 256 + tid;
        float4 v = base[idx];
        v.x += kap; v.y += kap; v.z += kap; v.w += kap;
        base[idx] = v;
        if (c == NC - 1 && idx >= NV - 16) {
            int q = (idx - (NV - 16)) * 4;
            last[q] = v.x; last[q + 1] = v.y; last[q + 2] = v.z; last[q + 3] = v.w;
        }
    }
    if (c == NC - 1) {
        __syncthreads();
        if (tid == 0) {
            float mx = last[0];
#pragma unroll
            for (int i = 1; i < NS; i++) mx = fmaxf(mx, last[i]);
            float tot = 0.0f;
#pragma unroll
            for (int i = 0; i < NS; i++) tot += __expf(last[i] - mx);
            logz[b] = mx + __logf(tot);
        }
    }
}

extern "C" void kernel_launch(void* const* d_in, const int* in_sizes, int n_in,
                              void* d_out, int out_size) {
    const float* trans = (const float*)d_in[0];  // (S,S) fp32
    const float* emis  = (const float*)d_in[1];  // (B,T,S) fp32
    // d_in[2] = seq_lens (unused by reference)
    float* alpha = (float*)d_out;                       // (B,T,S)
    float* logz  = alpha + (size_t)NB * NT * NS;        // (B,)

    dim3 g1(NC, NB);
    hmm_chunk_kernel<<<g1, NS>>>(trans, emis, alpha);
    hmm_offset_kernel<<<NB, 32>>>(alpha);
    dim3 g3(NC, NB);
    hmm_apply_kernel<<<g3, 256>>>(alpha, logz);
}

// round 17
// speedup vs baseline: 6.3663x; 1.0567x over previous
#include <cuda_runtime.h>
#include <cstdint>

#define NB 64
#define NT 4096
#define NS 64
#define CHUNK 128
#define NC (NT / CHUNK)   // 32 chunks; chunk c>0 warms up from t=(c-1)*CHUNK

__device__ float g_bnd[NB * NC * NS];   // g_bnd[b][c][:] = chunk (c-1)'s alpha' at t=c*CHUNK
__device__ float g_kappa[NB * NC];      // additive constant per chunk

__device__ __forceinline__ void fma2(unsigned long long &d, unsigned long long a, unsigned long long b) {
    asm("fma.rn.f32x2 %0, %1, %2, %0;" : "+l"(d) : "l"(a), "l"(b));
}
__device__ __forceinline__ unsigned long long add2(unsigned long long a, unsigned long long b) {
    unsigned long long d;
    asm("add.rn.f32x2 %0, %1, %2;" : "=l"(d) : "l"(a), "l"(b));
    return d;
}
__device__ __forceinline__ unsigned long long pk2(float lo, float hi) {
    unsigned long long d;
    asm("mov.b64 %0, {%1, %2};" : "=l"(d) : "f"(lo), "f"(hi));
    return d;
}

// ---------------- Pass 1: chunked forward; 4 warps/CTA = two batches x one chunk --------------
__global__ __launch_bounds__(128) void hmm_chunk_kernel(
    const float* __restrict__ trans,
    const float* __restrict__ emis,
    float* __restrict__ alpha_out)
{
    const int c = blockIdx.x;               // chunk
    const int h = threadIdx.x >> 6;         // half 0/1 -> warps {0,1} / {2,3} -> all 4 SMSPs
    const int b = blockIdx.y * 2 + h;       // batch
    const int j = threadIdx.x & (NS - 1);

    const int t0 = (c == 0) ? 0 : (c - 1) * CHUNK;     // warm-up start (c=0,1 exact)
    const int emit0 = c * CHUNK;
    const int emitEnd = (c + 1) * CHUNK;
    const int tlast = (c < NC - 1) ? emitEnd : (NT - 1);

    __shared__ __align__(16) float su[2][2][NS];  // [half][parity][state]
    __shared__ float ring[2][4];

    unsigned long long eA[NS / 2];
#pragma unroll
    for (int k = 0; k < NS / 2; k++) {
        float e0 = __expf(trans[(2 * k) * NS + j]);
        float e1 = __expf(trans[(2 * k + 1) * NS + j]);
        eA[k] = pk2(e0, e1);
    }

    const float* eb = emis + (size_t)b * NT * NS;
    float* ob = alpha_out + (size_t)b * NT * NS;
    float* bnd = g_bnd + ((size_t)b * NC + (c + 1)) * NS;   // written only when c < NC-1

    // --- init at t0: alpha'_{t0} = e_{t0} ---
    float a0 = eb[(size_t)t0 * NS + j];
    float n0 = eb[(size_t)t0 * NS];          // component 0 broadcast
    if (c == 0) ob[j] = a0;                  // emit row t=0
    if (j == 0) {                            // ring seeds r_{t0} = r_{t0-1} = r_{t0-2}
        ring[h][t0 & 3] = n0;
        ring[h][(t0 + 2) & 3] = n0;
        ring[h][(t0 + 3) & 3] = n0;
    }

    // slot (s-1)&3 holds e_s; init e_{t0+1}..e_{t0+4}
    float ebuf[4];
#pragma unroll
    for (int p = 0; p < 4; p++) ebuf[(t0 + p) & 3] = eb[(size_t)(t0 + 1 + p) * NS + j];

    __syncthreads();
    su[h][t0 & 1][j] = __expf(a0 - n0);                  // u(t0)
    float f = __expf(eb[(size_t)(t0 + 1) * NS + j]);     // f_{t0+1}
    __syncthreads();

    // exact stale-normalizer recurrence: u_t = exp(alpha_t - r_{t-2}); alpha_t = log s + r_{t-3} + e_t
#pragma unroll 2
    for (int t = t0 + 1; t <= tlast; t++) {
        const int buf = t & 1;
        const ulonglong2* sp = reinterpret_cast<const ulonglong2*>(&su[h][buf ^ 1][0]);
        unsigned long long acc0 = 0ull, acc1 = 0ull, acc2 = 0ull, acc3 = 0ull;
#pragma unroll
        for (int k = 0; k < 8; k++) {
            ulonglong2 qa = sp[2 * k];
            ulonglong2 qb = sp[2 * k + 1];
            fma2(acc0, qa.x, eA[4 * k + 0]);
            fma2(acc1, qa.y, eA[4 * k + 1]);
            fma2(acc2, qb.x, eA[4 * k + 2]);
            fma2(acc3, qb.y, eA[4 * k + 3]);
        }
        unsigned long long s2 = add2(add2(acc0, acc1), add2(acc2, acc3));
        float lo, hi;
        asm("mov.b64 {%0, %1}, %2;" : "=f"(lo), "=f"(hi) : "l"(s2));
        float s = lo + hi;

        su[h][buf][j] = s * f;         // u_t
        __syncthreads();

        float Nprev = ring[h][(t + 1) & 3];              // r_{t-3}
        float e_cur = ebuf[(t - 1) & 3];                 // e_t
        float aout = __logf(s) + Nprev + e_cur;          // alpha'_t[j]
        if (t >= emit0) {
            if (t < emitEnd) ob[(size_t)t * NS + j] = aout;
            else             bnd[j] = aout;              // boundary row for chunk c+1
        }
        if (j == 0) ring[h][t & 3] = aout;

        ebuf[(t - 1) & 3] = (t + 4 < NT) ? eb[(size_t)(t + 4) * NS + j] : 0.0f;
        float dM = ring[h][(t - 1) & 3] - ring[h][(t - 2) & 3];
        f = __expf(ebuf[t & 3] - dM);
    }
}

// ---------------- Pass 2: parallel deltas + warp prefix scan (one warp per batch) -------------
__global__ __launch_bounds__(32) void hmm_offset_kernel(const float* __restrict__ alpha)
{
    const int b = blockIdx.x;
    const int c = threadIdx.x;          // chunk 0..NC-1 (NC == 32)
    float d = 0.0f;
    if (c >= 1) {
        const float4* pb = reinterpret_cast<const float4*>(g_bnd + ((size_t)b * NC + c) * NS);
        const float4* pa = reinterpret_cast<const float4*>(alpha + ((size_t)b * NT + c * CHUNK) * NS);
        float acc = 0.0f;
#pragma unroll
        for (int k = 0; k < NS / 4; k++) {
            float4 vb = pb[k];
            float4 va = pa[k];
            acc += (vb.x - va.x) + (vb.y - va.y) + (vb.z - va.z) + (vb.w - va.w);
        }
        d = acc * (1.0f / NS);
    }
    // inclusive prefix sum over lanes -> kappa_c
#pragma unroll
    for (int o = 1; o < 32; o <<= 1) {
        float v = __shfl_up_sync(0xFFFFFFFFu, d, o);
        if (c >= o) d += v;
    }
    g_kappa[b * NC + c] = d;
}

// ---------------- Pass 3: apply constants + log_Z ----------------
__global__ __launch_bounds__(256) void hmm_apply_kernel(
    float* __restrict__ alpha, float* __restrict__ logz)
{
    const int c = blockIdx.x;
    const int b = blockIdx.y;
    const int tid = threadIdx.x;
    const float kap = g_kappa[b * NC + c];

    float4* base = reinterpret_cast<float4*>(alpha + ((size_t)b * NT + c * CHUNK) * NS);
    __shared__ float last[NS];
    const int NV = CHUNK * NS / 4;       // 2048 float4 per chunk block
#pragma unroll
    for (int k = 0; k < NV / 256; k++) {
        int idx = k * 256 + tid;
        float4 v = base[idx];
        v.x += kap; v.y += kap; v.z += kap; v.w += kap;
        base[idx] = v;
        if (c == NC - 1 && idx >= NV - 16) {
            int q = (idx - (NV - 16)) * 4;
            last[q] = v.x; last[q + 1] = v.y; last[q + 2] = v.z; last[q + 3] = v.w;
        }
    }
    if (c == NC - 1) {
        __syncthreads();
        if (tid == 0) {
            float mx = last[0];
#pragma unroll
            for (int i = 1; i < NS; i++) mx = fmaxf(mx, last[i]);
            float tot = 0.0f;
#pragma unroll
            for (int i = 0; i < NS; i++) tot += __expf(last[i] - mx);
            logz[b] = mx + __logf(tot);
        }
    }
}

extern "C" void kernel_launch(void* const* d_in, const int* in_sizes, int n_in,
                              void* d_out, int out_size) {
    const float* trans = (const float*)d_in[0];  // (S,S) fp32
    const float* emis  = (const float*)d_in[1];  // (B,T,S) fp32
    // d_in[2] = seq_lens (unused by reference)
    float* alpha = (float*)d_out;                       // (B,T,S)
    float* logz  = alpha + (size_t)NB * NT * NS;        // (B,)

    dim3 g1(NC, NB / 2);
    hmm_chunk_kernel<<<g1, 128>>>(trans, emis, alpha);
    hmm_offset_kernel<<<NB, 32>>>(alpha);
    dim3 g3(NC, NB);
    hmm_apply_kernel<<<g3, 256>>>(alpha, logz);
}